// round 1
// baseline (speedup 1.0000x reference)
#include <cuda_runtime.h>
#include <cuda_bf16.h>
#include <math.h>

// Problem constants
#define B 128
#define S 1024
#define H 256
#define V 256

// Scratch (device globals: allocation-free rule)
__device__ float g_hs[(size_t)B * S * H];   // hidden states [B,S,H]
__device__ float g_table[V * H];            // embed@Wxh^T + bxh + bhh
__device__ float g_context[B * H];          // attention context
__device__ float g_ctxout[B * V];           // context@Wfc^T + bfc
__device__ int   g_is64;                    // token dtype flag

// ---------------------------------------------------------------------------
// K0: detect whether x is int64 or int32. Reads only the first 512KB (safe
// under both interpretations). int64 => all odd 32-bit words are zero.
// ---------------------------------------------------------------------------
__global__ void k_detect(const unsigned int* __restrict__ xw) {
    __shared__ unsigned int red[32];
    unsigned int acc = 0;
    int tid = threadIdx.x;  // 1024 threads
    for (int i = tid; i < (B * S) / 2; i += 1024) acc |= xw[2 * i + 1];
    #pragma unroll
    for (int o = 16; o; o >>= 1) acc |= __shfl_xor_sync(0xffffffffu, acc, o);
    if ((tid & 31) == 0) red[tid >> 5] = acc;
    __syncthreads();
    if (tid == 0) {
        unsigned int a = 0;
        #pragma unroll
        for (int w = 0; w < 32; w++) a |= red[w];
        g_is64 = (a == 0) ? 1 : 0;
    }
}

// ---------------------------------------------------------------------------
// K1: table[v][j] = bxh[j] + bhh[j] + sum_k embed[v][k] * Wxh[j][k]
// ---------------------------------------------------------------------------
__global__ void k_table(const float* __restrict__ embed,
                        const float* __restrict__ Wxh,
                        const float* __restrict__ bxh,
                        const float* __restrict__ bhh) {
    int v = blockIdx.x;
    int j = threadIdx.x;
    __shared__ float es[H];
    es[j] = embed[v * H + j];
    __syncthreads();
    float a0 = bxh[j] + bhh[j], a1 = 0.f, a2 = 0.f, a3 = 0.f;
    const float4* w4 = (const float4*)(Wxh + j * H);
    const float4* e4 = (const float4*)es;
    #pragma unroll
    for (int i = 0; i < H / 4; i++) {
        float4 w = w4[i], e = e4[i];
        a0 += w.x * e.x; a1 += w.y * e.y; a2 += w.z * e.z; a3 += w.w * e.w;
    }
    g_table[v * H + j] = (a0 + a1) + (a2 + a3);
}

// ---------------------------------------------------------------------------
// K2: Elman recurrence. One CTA per batch, 256 threads (thread = feature j).
// Whh split: k in [0,192) in SMEM (transposed float4 [k4][j]), k in [192,256)
// in 16 float4 registers per thread. h kept in SMEM, written once per step.
// ---------------------------------------------------------------------------
#define K4_SMEM 48                              // 48 float4 groups = 192 k's
#define SMEM_RNN (K4_SMEM * 256 * 16 + 256 * 4) // 196608 + 1024 bytes

__global__ void __launch_bounds__(256, 1)
k_rnn(const void* __restrict__ xraw, const float* __restrict__ Whh) {
    extern __shared__ float4 sm4[];
    float4* w4  = sm4;                          // [48][256]
    float*  hsm = (float*)(sm4 + K4_SMEM * 256);
    const float4* h4 = (const float4*)hsm;

    int tid = threadIdx.x, b = blockIdx.x;

    // Load SMEM weight part: w4[k4*256+j] = Whh[j][4k4 .. 4k4+3]
    for (int i = tid; i < K4_SMEM * 256; i += 256) {
        int j = i & 255, k4 = i >> 8;
        w4[i] = *(const float4*)(Whh + j * H + (k4 << 2));
    }
    // Register tail: Whh[tid][192..255]
    float4 wr4[16];
    #pragma unroll
    for (int i = 0; i < 16; i++)
        wr4[i] = *(const float4*)(Whh + tid * H + 192 + 4 * i);

    hsm[tid] = 0.f;
    int is64 = g_is64;
    const long long* x64 = (const long long*)xraw;
    const int*       x32 = (const int*)xraw;
    __syncthreads();

    int tok0 = is64 ? (int)x64[(size_t)b * S] : x32[b * S];
    float tv = g_table[tok0 * H + tid];
    float* hs_out = g_hs + (size_t)b * S * H + tid;

    for (int t = 0; t < S; t++) {
        // Prefetch next token's table row while computing.
        float tvn = 0.f;
        if (t + 1 < S) {
            int tn = is64 ? (int)x64[(size_t)b * S + t + 1] : x32[b * S + t + 1];
            tvn = g_table[tn * H + tid];
        }
        float a0 = tv, a1 = 0.f, a2 = 0.f, a3 = 0.f;
        #pragma unroll 12
        for (int k4 = 0; k4 < K4_SMEM; k4++) {
            float4 w = w4[(k4 << 8) + tid];
            float4 hh = h4[k4];
            a0 += w.x * hh.x; a1 += w.y * hh.y; a2 += w.z * hh.z; a3 += w.w * hh.w;
        }
        #pragma unroll
        for (int i = 0; i < 16; i++) {
            float4 w = wr4[i];
            float4 hh = h4[K4_SMEM + i];
            a0 += w.x * hh.x; a1 += w.y * hh.y; a2 += w.z * hh.z; a3 += w.w * hh.w;
        }
        float hn = tanhf((a0 + a1) + (a2 + a3));
        __syncthreads();          // all reads of h_{t-1} done
        hsm[tid] = hn;
        hs_out[(size_t)t * H] = hn;
        tv = tvn;
        __syncthreads();          // h_t visible before next step's reads
    }
}

// ---------------------------------------------------------------------------
// K3: fused scores GEMV + online softmax over S + context accumulation.
// Grid (4, B): blockIdx.x = j-tile (64 features), blockIdx.y = batch.
// Thread layout: jj = tid>>2 (feature within tile), kg = tid&3 (k quarter).
// Wattn quarter-row lives in 16 float4 registers per thread.
// ---------------------------------------------------------------------------
__global__ void __launch_bounds__(256)
k_attn(const float* __restrict__ Wattn, const float* __restrict__ battn) {
    int b = blockIdx.y, jt = blockIdx.x;
    int tid = threadIdx.x, jj = tid >> 2, kg = tid & 3;
    int j = jt * 64 + jj;
    __shared__ float hrow[H];

    float4 wr[16];
    #pragma unroll
    for (int i = 0; i < 16; i++)
        wr[i] = *(const float4*)(Wattn + j * H + kg * 64 + 4 * i);
    float bb = battn[j];

    float m = -1e30f, l = 0.f, c = 0.f;
    const float* hbase = g_hs + (size_t)b * S * H;
    float r = hbase[tid];  // prefetch row 0

    for (int s = 0; s < S; s++) {
        __syncthreads();
        hrow[tid] = r;
        __syncthreads();
        if (s + 1 < S) r = hbase[(size_t)(s + 1) * H + tid];

        const float4* h4 = (const float4*)hrow;
        float p0 = 0.f, p1 = 0.f, p2 = 0.f, p3 = 0.f;
        #pragma unroll
        for (int i = 0; i < 16; i++) {
            float4 hh = h4[kg * 16 + i];
            float4 w = wr[i];
            p0 += w.x * hh.x; p1 += w.y * hh.y; p2 += w.z * hh.z; p3 += w.w * hh.w;
        }
        float sc = (p0 + p1) + (p2 + p3);
        sc += __shfl_xor_sync(0xffffffffu, sc, 1);
        sc += __shfl_xor_sync(0xffffffffu, sc, 2);
        sc += bb;

        float hj = hrow[j];
        float nm = fmaxf(m, sc);
        float scale = __expf(m - nm);
        float p = __expf(sc - nm);
        l = l * scale + p;
        c = c * scale + p * hj;
        m = nm;
    }
    if (kg == 0) g_context[b * H + j] = c / l;
}

// ---------------------------------------------------------------------------
// K3b: ctxout[b][v] = bfc[v] + sum_j context[b][j] * Wfc[v][j]
// ---------------------------------------------------------------------------
__global__ void k_ctxout(const float* __restrict__ Wfc,
                         const float* __restrict__ bfc) {
    int b = blockIdx.x, v = threadIdx.x;
    __shared__ float cs[H];
    cs[v] = g_context[b * H + v];
    __syncthreads();
    float a0 = bfc[v], a1 = 0.f, a2 = 0.f, a3 = 0.f;
    const float4* w4 = (const float4*)(Wfc + v * H);
    const float4* c4 = (const float4*)cs;
    #pragma unroll
    for (int i = 0; i < H / 4; i++) {
        float4 w = w4[i], cc = c4[i];
        a0 += w.x * cc.x; a1 += w.y * cc.y; a2 += w.z * cc.z; a3 += w.w * cc.w;
    }
    g_ctxout[b * V + v] = (a0 + a1) + (a2 + a3);
}

// ---------------------------------------------------------------------------
// K4: out[b,s,v] = sum_j hs[b,s,j]*Wfc[v,j] + ctxout[b,v]
// Same register-weight microkernel as K3.
// ---------------------------------------------------------------------------
__global__ void __launch_bounds__(256)
k_out(const float* __restrict__ Wfc, float* __restrict__ out) {
    int b = blockIdx.y, vt = blockIdx.x;
    int tid = threadIdx.x, vv = tid >> 2, kg = tid & 3;
    int v = vt * 64 + vv;
    __shared__ float hrow[H];

    float4 wr[16];
    #pragma unroll
    for (int i = 0; i < 16; i++)
        wr[i] = *(const float4*)(Wfc + v * H + kg * 64 + 4 * i);
    float cvx = g_ctxout[b * V + v];

    const float* hbase = g_hs + (size_t)b * S * H;
    float* obase = out + (size_t)b * S * V;
    float r = hbase[tid];

    for (int s = 0; s < S; s++) {
        __syncthreads();
        hrow[tid] = r;
        __syncthreads();
        if (s + 1 < S) r = hbase[(size_t)(s + 1) * H + tid];

        const float4* h4 = (const float4*)hrow;
        float p0 = 0.f, p1 = 0.f, p2 = 0.f, p3 = 0.f;
        #pragma unroll
        for (int i = 0; i < 16; i++) {
            float4 hh = h4[kg * 16 + i];
            float4 w = wr[i];
            p0 += w.x * hh.x; p1 += w.y * hh.y; p2 += w.z * hh.z; p3 += w.w * hh.w;
        }
        float d = (p0 + p1) + (p2 + p3);
        d += __shfl_xor_sync(0xffffffffu, d, 1);
        d += __shfl_xor_sync(0xffffffffu, d, 2);
        if (kg == 0) obase[(size_t)s * V + v] = d + cvx;
    }
}

// ---------------------------------------------------------------------------
extern "C" void kernel_launch(void* const* d_in, const int* in_sizes, int n_in,
                              void* d_out, int out_size) {
    const void*  x     = d_in[0];
    const float* embed = (const float*)d_in[1];
    const float* Wxh   = (const float*)d_in[2];
    const float* bxh   = (const float*)d_in[3];
    const float* Whh   = (const float*)d_in[4];
    const float* bhh   = (const float*)d_in[5];
    const float* Wattn = (const float*)d_in[6];
    const float* battn = (const float*)d_in[7];
    const float* Wfc   = (const float*)d_in[8];
    const float* bfc   = (const float*)d_in[9];
    float* out = (float*)d_out;

    cudaFuncSetAttribute(k_rnn, cudaFuncAttributeMaxDynamicSharedMemorySize,
                         SMEM_RNN);

    k_detect<<<1, 1024>>>((const unsigned int*)x);
    k_table<<<V, H>>>(embed, Wxh, bxh, bhh);
    k_rnn<<<B, 256, SMEM_RNN>>>(x, Whh);
    k_attn<<<dim3(4, B), 256>>>(Wattn, battn);
    k_ctxout<<<B, V>>>(Wfc, bfc);
    k_out<<<dim3(4, B), 256>>>(Wfc, out);
}

// round 2
// speedup vs baseline: 3.2217x; 3.2217x over previous
#include <cuda_runtime.h>
#include <cuda_bf16.h>
#include <math.h>

#define B 128
#define S 1024
#define H 256
#define V 256

// Scratch (device globals: allocation-free rule)
__device__ float g_hs[(size_t)B * S * H];   // hidden states [B,S,H]
__device__ float g_table[V * H];            // embed@Wxh^T + bxh + bhh
__device__ float g_context[B * H];          // attention context
__device__ float g_ctxout[B * V];           // context@Wfc^T + bfc
__device__ int   g_is64;                    // token dtype flag

// ---- packed f32x2 helpers (Blackwell) -------------------------------------
__device__ __forceinline__ unsigned long long fma2(unsigned long long a,
                                                   unsigned long long b,
                                                   unsigned long long c) {
    unsigned long long d;
    asm("fma.rn.f32x2 %0, %1, %2, %3;" : "=l"(d) : "l"(a), "l"(b), "l"(c));
    return d;
}
__device__ __forceinline__ float2 unpk(unsigned long long v) {
    float2 r;
    asm("mov.b64 {%0, %1}, %2;" : "=f"(r.x), "=f"(r.y) : "l"(v));
    return r;
}
__device__ __forceinline__ float tanhfast(float x) {
    float y;
    asm("tanh.approx.f32 %0, %1;" : "=f"(y) : "f"(x));
    return y;
}

// ---------------------------------------------------------------------------
// K0: detect int64 vs int32 tokens (odd 32-bit words all zero => int64)
// ---------------------------------------------------------------------------
__global__ void k_detect(const unsigned int* __restrict__ xw) {
    __shared__ unsigned int red[32];
    unsigned int acc = 0;
    int tid = threadIdx.x;
    for (int i = tid; i < (B * S) / 2; i += 1024) acc |= xw[2 * i + 1];
    #pragma unroll
    for (int o = 16; o; o >>= 1) acc |= __shfl_xor_sync(0xffffffffu, acc, o);
    if ((tid & 31) == 0) red[tid >> 5] = acc;
    __syncthreads();
    if (tid == 0) {
        unsigned int a = 0;
        #pragma unroll
        for (int w = 0; w < 32; w++) a |= red[w];
        g_is64 = (a == 0) ? 1 : 0;
    }
}

// ---------------------------------------------------------------------------
// K1: table[v][j] = bxh[j] + bhh[j] + sum_k embed[v][k] * Wxh[j][k]
// ---------------------------------------------------------------------------
__global__ void k_table(const float* __restrict__ embed,
                        const float* __restrict__ Wxh,
                        const float* __restrict__ bxh,
                        const float* __restrict__ bhh) {
    int v = blockIdx.x;
    int j = threadIdx.x;
    __shared__ float es[H];
    es[j] = embed[v * H + j];
    __syncthreads();
    float a0 = bxh[j] + bhh[j], a1 = 0.f, a2 = 0.f, a3 = 0.f;
    const float4* w4 = (const float4*)(Wxh + j * H);
    const float4* e4 = (const float4*)es;
    #pragma unroll
    for (int i = 0; i < H / 4; i++) {
        float4 w = w4[i], e = e4[i];
        a0 += w.x * e.x; a1 += w.y * e.y; a2 += w.z * e.z; a3 += w.w * e.w;
    }
    g_table[v * H + j] = (a0 + a1) + (a2 + a3);
}

// ---------------------------------------------------------------------------
// K2: Elman recurrence. One CTA per batch, 256 threads (thread = feature j).
// Whh[j][0:192) in registers as f32x2 (96 u64), Whh[j][192:256) via SMEM
// (transposed [g][j] float4). h double-buffered in SMEM -> 1 barrier/step.
// ---------------------------------------------------------------------------
#define KREG 192
#define KSMG 16                                   // (256-192)/4 float4 groups
#define SMEM_RNN (KSMG * 256 * 16 + 2 * 256 * 4)  // 65536 + 2048

__global__ void __launch_bounds__(256, 1)
k_rnn(const void* __restrict__ xraw, const float* __restrict__ Whh) {
    extern __shared__ char smraw[];
    ulonglong2* ws = (ulonglong2*)smraw;              // [16][256]
    float* hsm = (float*)(smraw + KSMG * 256 * 16);   // [2][256]

    int tid = threadIdx.x, b = blockIdx.x;

    // SMEM weight tail: ws[g*256+j] = Whh[j][192+4g .. 192+4g+3]
    for (int i = tid; i < KSMG * 256; i += 256) {
        int j = i & 255, g = i >> 8;
        ws[i] = *(const ulonglong2*)(Whh + j * H + KREG + 4 * g);
    }
    // Register weights: Whh[tid][0:192) packed as f32x2
    unsigned long long w[96];
    {
        const ulonglong2* p = (const ulonglong2*)(Whh + tid * H);
        #pragma unroll
        for (int i = 0; i < 48; i++) {
            ulonglong2 v = p[i];
            w[2 * i] = v.x; w[2 * i + 1] = v.y;
        }
    }
    hsm[tid] = 0.f;

    int is64 = g_is64;
    const long long* x64 = (const long long*)xraw;
    const int*       x32 = (const int*)xraw;
    __syncthreads();

    int tok0 = is64 ? (int)x64[(size_t)b * S] : x32[b * S];
    float tv = g_table[tok0 * H + tid];
    int tokn = (S > 1) ? (is64 ? (int)x64[(size_t)b * S + 1] : x32[b * S + 1]) : 0;
    float* hs_out = g_hs + (size_t)b * S * H + tid;

    for (int t = 0; t < S; t++) {
        // prefetch pipeline: table row for t+1, token id for t+2
        float tvn = (t + 1 < S) ? g_table[tokn * H + tid] : 0.f;
        int tokn2 = (t + 2 < S)
                    ? (is64 ? (int)x64[(size_t)b * S + t + 2] : x32[b * S + t + 2])
                    : 0;

        const ulonglong2* h2 = (const ulonglong2*)(hsm + ((t & 1) << 8));
        unsigned long long a0 = 0ull, a1 = 0ull, a2 = 0ull, a3 = 0ull;
        #pragma unroll
        for (int i = 0; i < 48; i++) {
            ulonglong2 hh = h2[i];
            a0 = fma2(w[2 * i],     hh.x, a0);
            a1 = fma2(w[2 * i + 1], hh.y, a1);
        }
        #pragma unroll
        for (int g = 0; g < KSMG; g++) {
            ulonglong2 hv = h2[48 + g];
            ulonglong2 wv = ws[(g << 8) + tid];
            a2 = fma2(wv.x, hv.x, a2);
            a3 = fma2(wv.y, hv.y, a3);
        }
        float2 u0 = unpk(a0), u1 = unpk(a1), u2 = unpk(a2), u3 = unpk(a3);
        float s = ((u0.x + u0.y) + (u1.x + u1.y)) +
                  ((u2.x + u2.y) + (u3.x + u3.y)) + tv;
        float hn = tanhfast(s);

        hsm[(((t & 1) ^ 1) << 8) + tid] = hn;   // write OTHER buffer: no WAR
        hs_out[(size_t)t * H] = hn;
        tv = tvn; tokn = tokn2;
        __syncthreads();                        // single barrier per step
    }
}

// ---------------------------------------------------------------------------
// Shared tile geometry for K3/K4: 8 s-rows per tile, padded quarters
// (68 floats per 64-float quarter) for conflict-free kg-blocked LDS.128.
// ---------------------------------------------------------------------------
#define ST 8
#define ROWP 272     // 4*68

// ---------------------------------------------------------------------------
// K3: fused scores GEMV + online softmax over S + context accumulation.
// Grid (4, B). Thread: jj = tid>>2 (feature in 64-tile), kg = tid&3 (k quarter).
// ---------------------------------------------------------------------------
__global__ void __launch_bounds__(256, 2)
k_attn(const float* __restrict__ Wattn, const float* __restrict__ battn) {
    __shared__ float tile[2][ST * ROWP];
    int b = blockIdx.y, jt = blockIdx.x;
    int tid = threadIdx.x, jj = tid >> 2, kg = tid & 3;
    int j = jt * 64 + jj;

    unsigned long long w[32];
    {
        const ulonglong2* wp = (const ulonglong2*)(Wattn + j * H + kg * 64);
        #pragma unroll
        for (int i = 0; i < 16; i++) {
            ulonglong2 v = wp[i];
            w[2 * i] = v.x; w[2 * i + 1] = v.y;
        }
    }
    float bb = battn[j];
    const float* hbase = g_hs + (size_t)b * S * H;
    int pcol = ((tid >> 6) * 68) + (tid & 63);   // padded column for loads

    // prologue: tile 0
    float r[ST];
    #pragma unroll
    for (int q = 0; q < ST; q++) r[q] = hbase[(size_t)q * H + tid];
    #pragma unroll
    for (int q = 0; q < ST; q++) tile[0][q * ROWP + pcol] = r[q];
    __syncthreads();

    float m = -1e30f, l = 0.f, c = 0.f;

    for (int it = 0; it < S / ST; it++) {
        int cur = it & 1;
        if (it + 1 < S / ST) {
            #pragma unroll
            for (int q = 0; q < ST; q++)
                r[q] = hbase[(size_t)((it + 1) * ST + q) * H + tid];
        }
        #pragma unroll
        for (int ss = 0; ss < ST; ss++) {
            const ulonglong2* h2 =
                (const ulonglong2*)(tile[cur] + ss * ROWP + kg * 68);
            unsigned long long a0 = 0ull, a1 = 0ull;
            #pragma unroll
            for (int i = 0; i < 16; i++) {
                ulonglong2 hh = h2[i];
                a0 = fma2(w[2 * i],     hh.x, a0);
                a1 = fma2(w[2 * i + 1], hh.y, a1);
            }
            float2 u0 = unpk(a0), u1 = unpk(a1);
            float sc = (u0.x + u0.y) + (u1.x + u1.y);
            sc += __shfl_xor_sync(0xffffffffu, sc, 1);
            sc += __shfl_xor_sync(0xffffffffu, sc, 2);
            sc += bb;

            float hj = tile[cur][ss * ROWP + jt * 68 + jj];
            float nm = fmaxf(m, sc);
            float scale = __expf(m - nm);
            float p = __expf(sc - nm);
            l = l * scale + p;
            c = c * scale + p * hj;
            m = nm;
        }
        if (it + 1 < S / ST) {
            #pragma unroll
            for (int q = 0; q < ST; q++)
                tile[cur ^ 1][q * ROWP + pcol] = r[q];
        }
        __syncthreads();
    }
    if (kg == 0) g_context[b * H + j] = c / l;
}

// ---------------------------------------------------------------------------
// K3b: ctxout[b][v] = bfc[v] + sum_j context[b][j] * Wfc[v][j]
// ---------------------------------------------------------------------------
__global__ void k_ctxout(const float* __restrict__ Wfc,
                         const float* __restrict__ bfc) {
    int b = blockIdx.x, v = threadIdx.x;
    __shared__ float cs[H];
    cs[v] = g_context[b * H + v];
    __syncthreads();
    float a0 = bfc[v], a1 = 0.f, a2 = 0.f, a3 = 0.f;
    const float4* w4 = (const float4*)(Wfc + v * H);
    const float4* c4 = (const float4*)cs;
    #pragma unroll
    for (int i = 0; i < H / 4; i++) {
        float4 w = w4[i], cc = c4[i];
        a0 += w.x * cc.x; a1 += w.y * cc.y; a2 += w.z * cc.z; a3 += w.w * cc.w;
    }
    g_ctxout[b * V + v] = (a0 + a1) + (a2 + a3);
}

// ---------------------------------------------------------------------------
// K4: out[b,s,v] = hs[b,s,:]·Wfc[v,:] + ctxout[b,v]. Same tiling as K3.
// ---------------------------------------------------------------------------
__global__ void __launch_bounds__(256, 2)
k_out(const float* __restrict__ Wfc, float* __restrict__ out) {
    __shared__ float tile[2][ST * ROWP];
    int b = blockIdx.y, vt = blockIdx.x;
    int tid = threadIdx.x, vv = tid >> 2, kg = tid & 3;
    int v = vt * 64 + vv;

    unsigned long long w[32];
    {
        const ulonglong2* wp = (const ulonglong2*)(Wfc + v * H + kg * 64);
        #pragma unroll
        for (int i = 0; i < 16; i++) {
            ulonglong2 x = wp[i];
            w[2 * i] = x.x; w[2 * i + 1] = x.y;
        }
    }
    float cvx = g_ctxout[b * V + v];
    const float* hbase = g_hs + (size_t)b * S * H;
    float* obase = out + (size_t)b * S * V;
    int pcol = ((tid >> 6) * 68) + (tid & 63);

    float r[ST];
    #pragma unroll
    for (int q = 0; q < ST; q++) r[q] = hbase[(size_t)q * H + tid];
    #pragma unroll
    for (int q = 0; q < ST; q++) tile[0][q * ROWP + pcol] = r[q];
    __syncthreads();

    for (int it = 0; it < S / ST; it++) {
        int cur = it & 1;
        if (it + 1 < S / ST) {
            #pragma unroll
            for (int q = 0; q < ST; q++)
                r[q] = hbase[(size_t)((it + 1) * ST + q) * H + tid];
        }
        #pragma unroll
        for (int ss = 0; ss < ST; ss++) {
            const ulonglong2* h2 =
                (const ulonglong2*)(tile[cur] + ss * ROWP + kg * 68);
            unsigned long long a0 = 0ull, a1 = 0ull;
            #pragma unroll
            for (int i = 0; i < 16; i++) {
                ulonglong2 hh = h2[i];
                a0 = fma2(w[2 * i],     hh.x, a0);
                a1 = fma2(w[2 * i + 1], hh.y, a1);
            }
            float2 u0 = unpk(a0), u1 = unpk(a1);
            float d = (u0.x + u0.y) + (u1.x + u1.y);
            d += __shfl_xor_sync(0xffffffffu, d, 1);
            d += __shfl_xor_sync(0xffffffffu, d, 2);
            if (kg == 0) obase[(size_t)(it * ST + ss) * V + v] = d + cvx;
        }
        if (it + 1 < S / ST) {
            #pragma unroll
            for (int q = 0; q < ST; q++)
                tile[cur ^ 1][q * ROWP + pcol] = r[q];
        }
        __syncthreads();
    }
}

// ---------------------------------------------------------------------------
extern "C" void kernel_launch(void* const* d_in, const int* in_sizes, int n_in,
                              void* d_out, int out_size) {
    const void*  x     = d_in[0];
    const float* embed = (const float*)d_in[1];
    const float* Wxh   = (const float*)d_in[2];
    const float* bxh   = (const float*)d_in[3];
    const float* Whh   = (const float*)d_in[4];
    const float* bhh   = (const float*)d_in[5];
    const float* Wattn = (const float*)d_in[6];
    const float* battn = (const float*)d_in[7];
    const float* Wfc   = (const float*)d_in[8];
    const float* bfc   = (const float*)d_in[9];
    float* out = (float*)d_out;

    cudaFuncSetAttribute(k_rnn, cudaFuncAttributeMaxDynamicSharedMemorySize,
                         SMEM_RNN);

    k_detect<<<1, 1024>>>((const unsigned int*)x);
    k_table<<<V, H>>>(embed, Wxh, bxh, bhh);
    k_rnn<<<B, 256, SMEM_RNN>>>(x, Whh);
    k_attn<<<dim3(4, B), 256>>>(Wattn, battn);
    k_ctxout<<<B, V>>>(Wfc, bfc);
    k_out<<<dim3(4, B), 256>>>(Wfc, out);
}

// round 3
// speedup vs baseline: 4.6330x; 1.4380x over previous
#include <cuda_runtime.h>
#include <cuda_bf16.h>
#include <math.h>

#define B 128
#define S 1024
#define H 256
#define V 256

// Scratch (device globals: allocation-free rule)
__device__ float g_hs[(size_t)B * S * H];   // hidden states [B,S,H]
__device__ float g_table[V * H];            // embed@Wxh^T + bxh + bhh
__device__ float g_context[B * H];          // attention context
__device__ float g_ctxout[B * V];           // context@Wfc^T + bfc
__device__ int   g_is64;                    // token dtype flag

typedef unsigned long long ull;

// ---- packed f32x2 helpers (Blackwell) -------------------------------------
__device__ __forceinline__ ull fma2(ull a, ull b, ull c) {
    ull d;
    asm("fma.rn.f32x2 %0, %1, %2, %3;" : "=l"(d) : "l"(a), "l"(b), "l"(c));
    return d;
}
__device__ __forceinline__ float2 unpk(ull v) {
    float2 r;
    asm("mov.b64 {%0, %1}, %2;" : "=f"(r.x), "=f"(r.y) : "l"(v));
    return r;
}
__device__ __forceinline__ float tanhfast(float x) {
    float y;
    asm("tanh.approx.f32 %0, %1;" : "=f"(y) : "f"(x));
    return y;
}
__device__ __forceinline__ float hsum2(ull a, ull b) {
    float2 u = unpk(a), v = unpk(b);
    return (u.x + u.y) + (v.x + v.y);
}

// ---------------------------------------------------------------------------
// K0: detect int64 vs int32 tokens (odd 32-bit words all zero => int64)
// ---------------------------------------------------------------------------
__global__ void k_detect(const unsigned int* __restrict__ xw) {
    __shared__ unsigned int red[32];
    unsigned int acc = 0;
    int tid = threadIdx.x;
    for (int i = tid; i < (B * S) / 2; i += 1024) acc |= xw[2 * i + 1];
    #pragma unroll
    for (int o = 16; o; o >>= 1) acc |= __shfl_xor_sync(0xffffffffu, acc, o);
    if ((tid & 31) == 0) red[tid >> 5] = acc;
    __syncthreads();
    if (tid == 0) {
        unsigned int a = 0;
        #pragma unroll
        for (int w = 0; w < 32; w++) a |= red[w];
        g_is64 = (a == 0) ? 1 : 0;
    }
}

// ---------------------------------------------------------------------------
// K1: table[v][j] = bxh[j] + bhh[j] + sum_k embed[v][k] * Wxh[j][k]
// ---------------------------------------------------------------------------
__global__ void k_table(const float* __restrict__ embed,
                        const float* __restrict__ Wxh,
                        const float* __restrict__ bxh,
                        const float* __restrict__ bhh) {
    int v = blockIdx.x;
    int j = threadIdx.x;
    __shared__ float es[H];
    es[j] = embed[v * H + j];
    __syncthreads();
    float a0 = bxh[j] + bhh[j], a1 = 0.f, a2 = 0.f, a3 = 0.f;
    const float4* w4 = (const float4*)(Wxh + j * H);
    const float4* e4 = (const float4*)es;
    #pragma unroll
    for (int i = 0; i < H / 4; i++) {
        float4 w = w4[i], e = e4[i];
        a0 += w.x * e.x; a1 += w.y * e.y; a2 += w.z * e.z; a3 += w.w * e.w;
    }
    g_table[v * H + j] = (a0 + a1) + (a2 + a3);
}

// ---------------------------------------------------------------------------
// K2: Elman recurrence. One CTA per batch, 256 threads (thread = feature j).
// Whh[j][0:192) in registers as f32x2, tail via SMEM. h double-buffered.
// ---------------------------------------------------------------------------
#define KREG 192
#define KSMG 16
#define SMEM_RNN (KSMG * 256 * 16 + 2 * 256 * 4)

__global__ void __launch_bounds__(256, 1)
k_rnn(const void* __restrict__ xraw, const float* __restrict__ Whh) {
    extern __shared__ char smraw[];
    ulonglong2* ws = (ulonglong2*)smraw;              // [16][256]
    float* hsm = (float*)(smraw + KSMG * 256 * 16);   // [2][256]

    int tid = threadIdx.x, b = blockIdx.x;

    for (int i = tid; i < KSMG * 256; i += 256) {
        int j = i & 255, g = i >> 8;
        ws[i] = *(const ulonglong2*)(Whh + j * H + KREG + 4 * g);
    }
    ull w[96];
    {
        const ulonglong2* p = (const ulonglong2*)(Whh + tid * H);
        #pragma unroll
        for (int i = 0; i < 48; i++) {
            ulonglong2 v = p[i];
            w[2 * i] = v.x; w[2 * i + 1] = v.y;
        }
    }
    hsm[tid] = 0.f;

    int is64 = g_is64;
    const long long* x64 = (const long long*)xraw;
    const int*       x32 = (const int*)xraw;
    __syncthreads();

    int tok0 = is64 ? (int)x64[(size_t)b * S] : x32[b * S];
    float tv = g_table[tok0 * H + tid];
    int tokn = is64 ? (int)x64[(size_t)b * S + 1] : x32[b * S + 1];
    float* hs_out = g_hs + (size_t)b * S * H + tid;

    for (int t = 0; t < S; t++) {
        float tvn = (t + 1 < S) ? g_table[tokn * H + tid] : 0.f;
        int tokn2 = (t + 2 < S)
                    ? (is64 ? (int)x64[(size_t)b * S + t + 2] : x32[b * S + t + 2])
                    : 0;

        const ulonglong2* h2 = (const ulonglong2*)(hsm + ((t & 1) << 8));
        ull a0 = 0ull, a1 = 0ull, a2 = 0ull, a3 = 0ull;
        #pragma unroll
        for (int i = 0; i < 48; i++) {
            ulonglong2 hh = h2[i];
            a0 = fma2(w[2 * i],     hh.x, a0);
            a1 = fma2(w[2 * i + 1], hh.y, a1);
        }
        #pragma unroll
        for (int g = 0; g < KSMG; g++) {
            ulonglong2 hv = h2[48 + g];
            ulonglong2 wv = ws[(g << 8) + tid];
            a2 = fma2(wv.x, hv.x, a2);
            a3 = fma2(wv.y, hv.y, a3);
        }
        float s = hsum2(a0, a1) + hsum2(a2, a3) + tv;
        float hn = tanhfast(s);

        hsm[(((t & 1) ^ 1) << 8) + tid] = hn;
        hs_out[(size_t)t * H] = hn;
        tv = tvn; tokn = tokn2;
        __syncthreads();
    }
}

// ---------------------------------------------------------------------------
// Tile geometry for K3/K4: 8 s-rows/tile, 68-float padded quarters.
// Staging: float4 LDG/STS, conflict-free.
// ---------------------------------------------------------------------------
#define ST 8
#define ROWP 272     // 4*68 floats per padded row

// ---------------------------------------------------------------------------
// K3: scores GEMV + online softmax + context. Grid (2,B), 256 thr.
// Thread: jj = tid>>2 -> 2 features (j0, j0+1); kg = tid&3 -> k quarter.
// ---------------------------------------------------------------------------
__global__ void __launch_bounds__(256, 1)
k_attn(const float* __restrict__ Wattn, const float* __restrict__ battn) {
    __shared__ float tile[2][ST * ROWP];
    int b = blockIdx.y, jt = blockIdx.x;
    int tid = threadIdx.x, jj = tid >> 2, kg = tid & 3;
    int j0 = jt * 128 + jj * 2;

    ull w0[32], w1[32];
    {
        const ulonglong2* p0 = (const ulonglong2*)(Wattn + (size_t)j0 * H + kg * 64);
        const ulonglong2* p1 = (const ulonglong2*)(Wattn + (size_t)(j0 + 1) * H + kg * 64);
        #pragma unroll
        for (int i = 0; i < 16; i++) {
            ulonglong2 v0 = p0[i], v1 = p1[i];
            w0[2 * i] = v0.x; w0[2 * i + 1] = v0.y;
            w1[2 * i] = v1.x; w1[2 * i + 1] = v1.y;
        }
    }
    float bb0 = battn[j0], bb1 = battn[j0 + 1];

    const float* hbase = g_hs + (size_t)b * S * H;
    int srow = tid >> 6;           // 0..3
    int scol = (tid & 63) * 4;     // 0..252
    int pofs = (scol >> 6) * 68 + (scol & 63);
    int hq = (j0 >> 6) * 68 + (j0 & 63);  // j0 even -> j0+1 in same quarter

    float4 r[2];
    #pragma unroll
    for (int q = 0; q < 2; q++)
        r[q] = *(const float4*)(hbase + (size_t)(q * 4 + srow) * H + scol);
    #pragma unroll
    for (int q = 0; q < 2; q++)
        *(float4*)(tile[0] + (q * 4 + srow) * ROWP + pofs) = r[q];
    __syncthreads();

    float m0 = -1e30f, l0 = 0.f, c0 = 0.f;
    float m1 = -1e30f, l1 = 0.f, c1 = 0.f;

    for (int it = 0; it < S / ST; it++) {
        int cur = it & 1;
        if (it + 1 < S / ST) {
            #pragma unroll
            for (int q = 0; q < 2; q++)
                r[q] = *(const float4*)(hbase +
                        (size_t)((it + 1) * ST + q * 4 + srow) * H + scol);
        }
        #pragma unroll
        for (int ss = 0; ss < ST; ss++) {
            const ulonglong2* h2 =
                (const ulonglong2*)(tile[cur] + ss * ROWP + kg * 68);
            ull a0 = 0ull, a1 = 0ull, d0 = 0ull, d1 = 0ull;
            #pragma unroll
            for (int i = 0; i < 16; i++) {
                ulonglong2 hh = h2[i];
                a0 = fma2(w0[2 * i],     hh.x, a0);
                a1 = fma2(w0[2 * i + 1], hh.y, a1);
                d0 = fma2(w1[2 * i],     hh.x, d0);
                d1 = fma2(w1[2 * i + 1], hh.y, d1);
            }
            float sc0 = hsum2(a0, a1);
            float sc1 = hsum2(d0, d1);
            sc0 += __shfl_xor_sync(0xffffffffu, sc0, 1);
            sc0 += __shfl_xor_sync(0xffffffffu, sc0, 2);
            sc1 += __shfl_xor_sync(0xffffffffu, sc1, 1);
            sc1 += __shfl_xor_sync(0xffffffffu, sc1, 2);
            sc0 += bb0; sc1 += bb1;

            float hj0 = tile[cur][ss * ROWP + hq];
            float hj1 = tile[cur][ss * ROWP + hq + 1];

            float nm0 = fmaxf(m0, sc0);
            float s0 = __expf(m0 - nm0), p0 = __expf(sc0 - nm0);
            l0 = l0 * s0 + p0; c0 = c0 * s0 + p0 * hj0; m0 = nm0;

            float nm1 = fmaxf(m1, sc1);
            float s1 = __expf(m1 - nm1), p1 = __expf(sc1 - nm1);
            l1 = l1 * s1 + p1; c1 = c1 * s1 + p1 * hj1; m1 = nm1;
        }
        if (it + 1 < S / ST) {
            #pragma unroll
            for (int q = 0; q < 2; q++)
                *(float4*)(tile[cur ^ 1] + (q * 4 + srow) * ROWP + pofs) = r[q];
        }
        __syncthreads();
    }
    if (kg == 0) {
        g_context[b * H + j0]     = c0 / l0;
        g_context[b * H + j0 + 1] = c1 / l1;
    }
}

// ---------------------------------------------------------------------------
// K3b: ctxout[b][v] = bfc[v] + sum_j context[b][j] * Wfc[v][j]
// ---------------------------------------------------------------------------
__global__ void k_ctxout(const float* __restrict__ Wfc,
                         const float* __restrict__ bfc) {
    int b = blockIdx.x, v = threadIdx.x;
    __shared__ float cs[H];
    cs[v] = g_context[b * H + v];
    __syncthreads();
    float a0 = bfc[v], a1 = 0.f, a2 = 0.f, a3 = 0.f;
    const float4* w4 = (const float4*)(Wfc + v * H);
    const float4* c4 = (const float4*)cs;
    #pragma unroll
    for (int i = 0; i < H / 4; i++) {
        float4 w = w4[i], cc = c4[i];
        a0 += w.x * cc.x; a1 += w.y * cc.y; a2 += w.z * cc.z; a3 += w.w * cc.w;
    }
    g_ctxout[b * V + v] = (a0 + a1) + (a2 + a3);
}

// ---------------------------------------------------------------------------
// K4: out[b,s,v] = hs[b,s,:]·Wfc[v,:] + ctxout[b,v]. Grid (2,B), 2 v/thread.
// ---------------------------------------------------------------------------
__global__ void __launch_bounds__(256, 1)
k_out(const float* __restrict__ Wfc, float* __restrict__ out) {
    __shared__ float tile[2][ST * ROWP];
    int b = blockIdx.y, vt = blockIdx.x;
    int tid = threadIdx.x, vv = tid >> 2, kg = tid & 3;
    int v0 = vt * 128 + vv * 2;

    ull w0[32], w1[32];
    {
        const ulonglong2* p0 = (const ulonglong2*)(Wfc + (size_t)v0 * H + kg * 64);
        const ulonglong2* p1 = (const ulonglong2*)(Wfc + (size_t)(v0 + 1) * H + kg * 64);
        #pragma unroll
        for (int i = 0; i < 16; i++) {
            ulonglong2 x0 = p0[i], x1 = p1[i];
            w0[2 * i] = x0.x; w0[2 * i + 1] = x0.y;
            w1[2 * i] = x1.x; w1[2 * i + 1] = x1.y;
        }
    }
    float cv0 = g_ctxout[b * V + v0];
    float cv1 = g_ctxout[b * V + v0 + 1];

    const float* hbase = g_hs + (size_t)b * S * H;
    float* obase = out + (size_t)b * S * V;
    int srow = tid >> 6;
    int scol = (tid & 63) * 4;
    int pofs = (scol >> 6) * 68 + (scol & 63);

    float4 r[2];
    #pragma unroll
    for (int q = 0; q < 2; q++)
        r[q] = *(const float4*)(hbase + (size_t)(q * 4 + srow) * H + scol);
    #pragma unroll
    for (int q = 0; q < 2; q++)
        *(float4*)(tile[0] + (q * 4 + srow) * ROWP + pofs) = r[q];
    __syncthreads();

    for (int it = 0; it < S / ST; it++) {
        int cur = it & 1;
        if (it + 1 < S / ST) {
            #pragma unroll
            for (int q = 0; q < 2; q++)
                r[q] = *(const float4*)(hbase +
                        (size_t)((it + 1) * ST + q * 4 + srow) * H + scol);
        }
        #pragma unroll
        for (int ss = 0; ss < ST; ss++) {
            const ulonglong2* h2 =
                (const ulonglong2*)(tile[cur] + ss * ROWP + kg * 68);
            ull a0 = 0ull, a1 = 0ull, d0 = 0ull, d1 = 0ull;
            #pragma unroll
            for (int i = 0; i < 16; i++) {
                ulonglong2 hh = h2[i];
                a0 = fma2(w0[2 * i],     hh.x, a0);
                a1 = fma2(w0[2 * i + 1], hh.y, a1);
                d0 = fma2(w1[2 * i],     hh.x, d0);
                d1 = fma2(w1[2 * i + 1], hh.y, d1);
            }
            float o0 = hsum2(a0, a1);
            float o1 = hsum2(d0, d1);
            o0 += __shfl_xor_sync(0xffffffffu, o0, 1);
            o0 += __shfl_xor_sync(0xffffffffu, o0, 2);
            o1 += __shfl_xor_sync(0xffffffffu, o1, 1);
            o1 += __shfl_xor_sync(0xffffffffu, o1, 2);
            if (kg == 0) {
                float2 ov = make_float2(o0 + cv0, o1 + cv1);
                *(float2*)(obase + (size_t)(it * ST + ss) * V + v0) = ov;
            }
        }
        if (it + 1 < S / ST) {
            #pragma unroll
            for (int q = 0; q < 2; q++)
                *(float4*)(tile[cur ^ 1] + (q * 4 + srow) * ROWP + pofs) = r[q];
        }
        __syncthreads();
    }
}

// ---------------------------------------------------------------------------
extern "C" void kernel_launch(void* const* d_in, const int* in_sizes, int n_in,
                              void* d_out, int out_size) {
    const void*  x     = d_in[0];
    const float* embed = (const float*)d_in[1];
    const float* Wxh   = (const float*)d_in[2];
    const float* bxh   = (const float*)d_in[3];
    const float* Whh   = (const float*)d_in[4];
    const float* bhh   = (const float*)d_in[5];
    const float* Wattn = (const float*)d_in[6];
    const float* battn = (const float*)d_in[7];
    const float* Wfc   = (const float*)d_in[8];
    const float* bfc   = (const float*)d_in[9];
    float* out = (float*)d_out;

    cudaFuncSetAttribute(k_rnn, cudaFuncAttributeMaxDynamicSharedMemorySize,
                         SMEM_RNN);

    k_detect<<<1, 1024>>>((const unsigned int*)x);
    k_table<<<V, H>>>(embed, Wxh, bxh, bhh);
    k_rnn<<<B, 256, SMEM_RNN>>>(x, Whh);
    k_attn<<<dim3(2, B), 256>>>(Wattn, battn);
    k_ctxout<<<B, V>>>(Wfc, bfc);
    k_out<<<dim3(2, B), 256>>>(Wfc, out);
}

// round 4
// speedup vs baseline: 5.8009x; 1.2521x over previous
#include <cuda_runtime.h>
#include <cuda_bf16.h>
#include <math.h>

#define B 128
#define S 1024
#define H 256
#define V 256

// Scratch (device globals: allocation-free rule)
__device__ float g_hs[(size_t)B * S * H];   // hidden states [B,S,H]
__device__ float g_table[V * H];            // embed@Wxh^T + bxh + bhh
__device__ float g_context[B * H];          // attention context
__device__ float g_ctxout[B * V];           // context@Wfc^T + bfc
__device__ int   g_is64;                    // token dtype flag

typedef unsigned long long ull;

// ---- packed f32x2 helpers (Blackwell) -------------------------------------
__device__ __forceinline__ ull fma2(ull a, ull b, ull c) {
    ull d;
    asm("fma.rn.f32x2 %0, %1, %2, %3;" : "=l"(d) : "l"(a), "l"(b), "l"(c));
    return d;
}
__device__ __forceinline__ float2 unpk(ull v) {
    float2 r;
    asm("mov.b64 {%0, %1}, %2;" : "=f"(r.x), "=f"(r.y) : "l"(v));
    return r;
}
__device__ __forceinline__ ull pk2(float a, float b) {
    ull r;
    asm("mov.b64 %0, {%1, %2};" : "=l"(r) : "f"(a), "f"(b));
    return r;
}
__device__ __forceinline__ float tanhfast(float x) {
    float y;
    asm("tanh.approx.f32 %0, %1;" : "=f"(y) : "f"(x));
    return y;
}
__device__ __forceinline__ float hsum2(ull a, ull b) {
    float2 u = unpk(a), v = unpk(b);
    return (u.x + u.y) + (v.x + v.y);
}

// ---------------------------------------------------------------------------
// K0: detect int64 vs int32 tokens (odd 32-bit words all zero => int64)
// ---------------------------------------------------------------------------
__global__ void k_detect(const unsigned int* __restrict__ xw) {
    __shared__ unsigned int red[32];
    unsigned int acc = 0;
    int tid = threadIdx.x;
    for (int i = tid; i < (B * S) / 2; i += 1024) acc |= xw[2 * i + 1];
    #pragma unroll
    for (int o = 16; o; o >>= 1) acc |= __shfl_xor_sync(0xffffffffu, acc, o);
    if ((tid & 31) == 0) red[tid >> 5] = acc;
    __syncthreads();
    if (tid == 0) {
        unsigned int a = 0;
        #pragma unroll
        for (int w = 0; w < 32; w++) a |= red[w];
        g_is64 = (a == 0) ? 1 : 0;
    }
}

// ---------------------------------------------------------------------------
// K1: table[v][j] = bxh[j] + bhh[j] + sum_k embed[v][k] * Wxh[j][k]
// ---------------------------------------------------------------------------
__global__ void k_table(const float* __restrict__ embed,
                        const float* __restrict__ Wxh,
                        const float* __restrict__ bxh,
                        const float* __restrict__ bhh) {
    int v = blockIdx.x;
    int j = threadIdx.x;
    __shared__ float es[H];
    es[j] = embed[v * H + j];
    __syncthreads();
    float a0 = bxh[j] + bhh[j], a1 = 0.f, a2 = 0.f, a3 = 0.f;
    const float4* w4 = (const float4*)(Wxh + j * H);
    const float4* e4 = (const float4*)es;
    #pragma unroll
    for (int i = 0; i < H / 4; i++) {
        float4 w = w4[i], e = e4[i];
        a0 += w.x * e.x; a1 += w.y * e.y; a2 += w.z * e.z; a3 += w.w * e.w;
    }
    g_table[v * H + j] = (a0 + a1) + (a2 + a3);
}

// ---------------------------------------------------------------------------
// K2: Elman recurrence (unchanged from R3).
// ---------------------------------------------------------------------------
#define KREG 192
#define KSMG 16
#define SMEM_RNN (KSMG * 256 * 16 + 2 * 256 * 4)

__global__ void __launch_bounds__(256, 1)
k_rnn(const void* __restrict__ xraw, const float* __restrict__ Whh) {
    extern __shared__ char smraw[];
    ulonglong2* ws = (ulonglong2*)smraw;
    float* hsm = (float*)(smraw + KSMG * 256 * 16);

    int tid = threadIdx.x, b = blockIdx.x;

    for (int i = tid; i < KSMG * 256; i += 256) {
        int j = i & 255, g = i >> 8;
        ws[i] = *(const ulonglong2*)(Whh + j * H + KREG + 4 * g);
    }
    ull w[96];
    {
        const ulonglong2* p = (const ulonglong2*)(Whh + tid * H);
        #pragma unroll
        for (int i = 0; i < 48; i++) {
            ulonglong2 v = p[i];
            w[2 * i] = v.x; w[2 * i + 1] = v.y;
        }
    }
    hsm[tid] = 0.f;

    int is64 = g_is64;
    const long long* x64 = (const long long*)xraw;
    const int*       x32 = (const int*)xraw;
    __syncthreads();

    int tok0 = is64 ? (int)x64[(size_t)b * S] : x32[b * S];
    float tv = g_table[tok0 * H + tid];
    int tokn = is64 ? (int)x64[(size_t)b * S + 1] : x32[b * S + 1];
    float* hs_out = g_hs + (size_t)b * S * H + tid;

    for (int t = 0; t < S; t++) {
        float tvn = (t + 1 < S) ? g_table[tokn * H + tid] : 0.f;
        int tokn2 = (t + 2 < S)
                    ? (is64 ? (int)x64[(size_t)b * S + t + 2] : x32[b * S + t + 2])
                    : 0;

        const ulonglong2* h2 = (const ulonglong2*)(hsm + ((t & 1) << 8));
        ull a0 = 0ull, a1 = 0ull, a2 = 0ull, a3 = 0ull;
        #pragma unroll
        for (int i = 0; i < 48; i++) {
            ulonglong2 hh = h2[i];
            a0 = fma2(w[2 * i],     hh.x, a0);
            a1 = fma2(w[2 * i + 1], hh.y, a1);
        }
        #pragma unroll
        for (int g = 0; g < KSMG; g++) {
            ulonglong2 hv = h2[48 + g];
            ulonglong2 wv = ws[(g << 8) + tid];
            a2 = fma2(wv.x, hv.x, a2);
            a3 = fma2(wv.y, hv.y, a3);
        }
        float s = hsum2(a0, a1) + hsum2(a2, a3) + tv;
        float hn = tanhfast(s);

        hsm[(((t & 1) ^ 1) << 8) + tid] = hn;
        hs_out[(size_t)t * H] = hn;
        tv = tvn; tokn = tokn2;
        __syncthreads();
    }
}

// ---------------------------------------------------------------------------
// GEMM geometry (k_attn / k_out): CTA = 64 rows (j/v) x 128 s, K=256.
// SMEM: W tile packed as k2-pairs [128 k2][64 j] (pitch 66 ull, 16B-aligned),
//       h tile double-buffered [16 k2][128 s] (pitch 130 ull).
// Thread: m = tid&15 -> rows {2m,2m+1,2m+32,2m+33}; g = tid>>4 -> s0 = 8g.
// Inner loop per k2: 2+4 LDS.128 + 32 fma2 (both halves = even/odd k).
// ---------------------------------------------------------------------------
#define WPITCH 66
#define HPITCH 130
#define WT_ULL (128 * WPITCH)            // 8448
#define HT_ULL (16 * HPITCH)             // 2080
#define SMEM_GEMM ((WT_ULL + 2 * HT_ULL) * 8)   // 100864 bytes

// Stage W tile (rows jbase..jbase+63, all 256 k) into wt, k-pair packed.
__device__ __forceinline__ void stage_w(ull* wt, const float* __restrict__ W,
                                        int jbase, int tid) {
    int kcol = tid & 63, jl = tid >> 6;
    #pragma unroll
    for (int p = 0; p < 16; p++) {
        int j = jl + p * 4;
        float4 wv = *(const float4*)(W + (size_t)(jbase + j) * H + kcol * 4);
        wt[(2 * kcol)     * WPITCH + j] = pk2(wv.x, wv.y);
        wt[(2 * kcol + 1) * WPITCH + j] = pk2(wv.z, wv.w);
    }
}

__device__ __forceinline__ void ldg_h(float4* r, const float4* __restrict__ hb4,
                                      int sch, int kc, int tid) {
    int col = tid & 7, srow = tid >> 3;
    #pragma unroll
    for (int q = 0; q < 4; q++)
        r[q] = hb4[(size_t)(sch * 128 + srow + 32 * q) * 64 + kc * 8 + col];
}
__device__ __forceinline__ void sts_h(ull* ht, const float4* r, int tid) {
    int col = tid & 7, srow = tid >> 3;
    #pragma unroll
    for (int q = 0; q < 4; q++) {
        ht[(2 * col)     * HPITCH + srow + 32 * q] = pk2(r[q].x, r[q].y);
        ht[(2 * col + 1) * HPITCH + srow + 32 * q] = pk2(r[q].z, r[q].w);
    }
}

__device__ __forceinline__ void gemm_chunk(ull* acc, const ull* __restrict__ wt,
                                           const ull* __restrict__ hb,
                                           int kc, int m, int s0) {
    #pragma unroll
    for (int k = 0; k < 16; k++) {
        const ull* wr = wt + (kc * 16 + k) * WPITCH;
        ulonglong2 wa = *(const ulonglong2*)(wr + 2 * m);
        ulonglong2 wb = *(const ulonglong2*)(wr + 32 + 2 * m);
        const ull* hr = hb + k * HPITCH + s0;
        ulonglong2 h0 = *(const ulonglong2*)(hr);
        ulonglong2 h1 = *(const ulonglong2*)(hr + 2);
        ulonglong2 h2 = *(const ulonglong2*)(hr + 4);
        ulonglong2 h3 = *(const ulonglong2*)(hr + 6);
        ull wv[4] = {wa.x, wa.y, wb.x, wb.y};
        ull hv[8] = {h0.x, h0.y, h1.x, h1.y, h2.x, h2.y, h3.x, h3.y};
        #pragma unroll
        for (int jx = 0; jx < 4; jx++)
            #pragma unroll
            for (int sx = 0; sx < 8; sx++)
                acc[jx * 8 + sx] = fma2(wv[jx], hv[sx], acc[jx * 8 + sx]);
    }
}

// ---------------------------------------------------------------------------
// K3: scores GEMM + online softmax + context. Grid (4, B).
// ---------------------------------------------------------------------------
__global__ void __launch_bounds__(256, 2)
k_attn(const float* __restrict__ Wattn, const float* __restrict__ battn) {
    extern __shared__ ull smg[];
    ull* wt = smg;
    ull* ht0 = smg + WT_ULL;
    ull* ht1 = ht0 + HT_ULL;

    int b = blockIdx.y, jbase = blockIdx.x * 64;
    int tid = threadIdx.x, m = tid & 15, g = tid >> 4, s0 = g * 8;
    int jA[4] = {2 * m, 2 * m + 1, 2 * m + 32, 2 * m + 33};

    stage_w(wt, Wattn, jbase, tid);

    float bb[4];
    #pragma unroll
    for (int jx = 0; jx < 4; jx++) bb[jx] = battn[jbase + jA[jx]];

    const float* hb = g_hs + (size_t)b * S * H;
    const float4* hb4 = (const float4*)hb;

    float mx[4] = {-1e30f, -1e30f, -1e30f, -1e30f};
    float li[4] = {0.f, 0.f, 0.f, 0.f};
    float ci[4] = {0.f, 0.f, 0.f, 0.f};

    float4 r[4];
    for (int sch = 0; sch < S / 128; sch++) {
        ull acc[32];
        #pragma unroll
        for (int i = 0; i < 32; i++) acc[i] = 0ull;

        ldg_h(r, hb4, sch, 0, tid);
        sts_h(ht0, r, tid);
        __syncthreads();

        for (int kc = 0; kc < 8; kc++) {
            if (kc < 7) ldg_h(r, hb4, sch, kc + 1, tid);
            gemm_chunk(acc, wt, (kc & 1) ? ht1 : ht0, kc, m, s0);
            if (kc < 7) {
                sts_h((kc & 1) ? ht0 : ht1, r, tid);
                __syncthreads();
            }
        }

        // epilogue: online softmax over this chunk's 8 s values per feature
        #pragma unroll
        for (int jx = 0; jx < 4; jx++) {
            float sc[8];
            #pragma unroll
            for (int sx = 0; sx < 8; sx++) {
                float2 u = unpk(acc[jx * 8 + sx]);
                sc[sx] = u.x + u.y + bb[jx];
            }
            float cm = sc[0];
            #pragma unroll
            for (int sx = 1; sx < 8; sx++) cm = fmaxf(cm, sc[sx]);
            float nm = fmaxf(mx[jx], cm);
            float scale = __expf(mx[jx] - nm);
            float ls = 0.f, cs = 0.f;
            #pragma unroll
            for (int sx = 0; sx < 8; sx++) {
                int sglob = sch * 128 + s0 + sx;
                float hj = hb[(size_t)sglob * H + jbase + jA[jx]];
                float p = __expf(sc[sx] - nm);
                ls += p; cs += p * hj;
            }
            li[jx] = li[jx] * scale + ls;
            ci[jx] = ci[jx] * scale + cs;
            mx[jx] = nm;
        }
        __syncthreads();   // before next chunk's staging reuses ht0
    }

    // cross-thread merge: 16 groups (g) share each j
    float* Mm = (float*)ht0;
    float* Ml = Mm + 64 * 17;
    float* Mc = Ml + 64 * 17;
    #pragma unroll
    for (int jx = 0; jx < 4; jx++) {
        int idx = jA[jx] * 17 + g;
        Mm[idx] = mx[jx]; Ml[idx] = li[jx]; Mc[idx] = ci[jx];
    }
    __syncthreads();
    if (tid < 64) {
        float bm = -1e30f;
        #pragma unroll
        for (int q = 0; q < 16; q++) bm = fmaxf(bm, Mm[tid * 17 + q]);
        float L = 0.f, C = 0.f;
        #pragma unroll
        for (int q = 0; q < 16; q++) {
            float e = __expf(Mm[tid * 17 + q] - bm);
            L += Ml[tid * 17 + q] * e;
            C += Mc[tid * 17 + q] * e;
        }
        g_context[b * H + jbase + tid] = C / L;
    }
}

// ---------------------------------------------------------------------------
// K3b: ctxout[b][v] = bfc[v] + sum_j context[b][j] * Wfc[v][j]
// ---------------------------------------------------------------------------
__global__ void k_ctxout(const float* __restrict__ Wfc,
                         const float* __restrict__ bfc) {
    int b = blockIdx.x, v = threadIdx.x;
    __shared__ float cs[H];
    cs[v] = g_context[b * H + v];
    __syncthreads();
    float a0 = bfc[v], a1 = 0.f, a2 = 0.f, a3 = 0.f;
    const float4* w4 = (const float4*)(Wfc + v * H);
    const float4* c4 = (const float4*)cs;
    #pragma unroll
    for (int i = 0; i < H / 4; i++) {
        float4 w = w4[i], cc = c4[i];
        a0 += w.x * cc.x; a1 += w.y * cc.y; a2 += w.z * cc.z; a3 += w.w * cc.w;
    }
    g_ctxout[b * V + v] = (a0 + a1) + (a2 + a3);
}

// ---------------------------------------------------------------------------
// K4: out[b,s,v] = hs[b,s,:]·Wfc[v,:] + ctxout[b,v]. Grid (4, B).
// ---------------------------------------------------------------------------
__global__ void __launch_bounds__(256, 2)
k_out(const float* __restrict__ Wfc, float* __restrict__ out) {
    extern __shared__ ull smg[];
    ull* wt = smg;
    ull* ht0 = smg + WT_ULL;
    ull* ht1 = ht0 + HT_ULL;

    int b = blockIdx.y, vbase = blockIdx.x * 64;
    int tid = threadIdx.x, m = tid & 15, g = tid >> 4, s0 = g * 8;
    int vA[4] = {2 * m, 2 * m + 1, 2 * m + 32, 2 * m + 33};

    stage_w(wt, Wfc, vbase, tid);

    float cv[4];
    #pragma unroll
    for (int jx = 0; jx < 4; jx++) cv[jx] = g_ctxout[b * V + vbase + vA[jx]];

    const float4* hb4 = (const float4*)(g_hs + (size_t)b * S * H);
    float* ob = out + (size_t)b * S * V;

    float4 r[4];
    for (int sch = 0; sch < S / 128; sch++) {
        ull acc[32];
        #pragma unroll
        for (int i = 0; i < 32; i++) acc[i] = 0ull;

        ldg_h(r, hb4, sch, 0, tid);
        sts_h(ht0, r, tid);
        __syncthreads();

        for (int kc = 0; kc < 8; kc++) {
            if (kc < 7) ldg_h(r, hb4, sch, kc + 1, tid);
            gemm_chunk(acc, wt, (kc & 1) ? ht1 : ht0, kc, m, s0);
            if (kc < 7) {
                sts_h((kc & 1) ? ht0 : ht1, r, tid);
                __syncthreads();
            }
        }

        #pragma unroll
        for (int sx = 0; sx < 8; sx++) {
            int sglob = sch * 128 + s0 + sx;
            float2 u0 = unpk(acc[0 * 8 + sx]), u1 = unpk(acc[1 * 8 + sx]);
            float2 u2 = unpk(acc[2 * 8 + sx]), u3 = unpk(acc[3 * 8 + sx]);
            float2 oA = make_float2(u0.x + u0.y + cv[0], u1.x + u1.y + cv[1]);
            float2 oB = make_float2(u2.x + u2.y + cv[2], u3.x + u3.y + cv[3]);
            *(float2*)(ob + (size_t)sglob * V + vbase + 2 * m)      = oA;
            *(float2*)(ob + (size_t)sglob * V + vbase + 2 * m + 32) = oB;
        }
        __syncthreads();
    }
}

// ---------------------------------------------------------------------------
extern "C" void kernel_launch(void* const* d_in, const int* in_sizes, int n_in,
                              void* d_out, int out_size) {
    const void*  x     = d_in[0];
    const float* embed = (const float*)d_in[1];
    const float* Wxh   = (const float*)d_in[2];
    const float* bxh   = (const float*)d_in[3];
    const float* Whh   = (const float*)d_in[4];
    const float* bhh   = (const float*)d_in[5];
    const float* Wattn = (const float*)d_in[6];
    const float* battn = (const float*)d_in[7];
    const float* Wfc   = (const float*)d_in[8];
    const float* bfc   = (const float*)d_in[9];
    float* out = (float*)d_out;

    cudaFuncSetAttribute(k_rnn, cudaFuncAttributeMaxDynamicSharedMemorySize,
                         SMEM_RNN);
    cudaFuncSetAttribute(k_attn, cudaFuncAttributeMaxDynamicSharedMemorySize,
                         SMEM_GEMM);
    cudaFuncSetAttribute(k_out, cudaFuncAttributeMaxDynamicSharedMemorySize,
                         SMEM_GEMM);

    k_detect<<<1, 1024>>>((const unsigned int*)x);
    k_table<<<V, H>>>(embed, Wxh, bxh, bhh);
    k_rnn<<<B, 256, SMEM_RNN>>>(x, Whh);
    k_attn<<<dim3(4, B), 256, SMEM_GEMM>>>(Wattn, battn);
    k_ctxout<<<B, V>>>(Wfc, bfc);
    k_out<<<dim3(4, B), 256, SMEM_GEMM>>>(Wfc, out);
}

// round 7
// speedup vs baseline: 7.3920x; 1.2743x over previous
#include <cuda_runtime.h>
#include <cuda_bf16.h>
#include <math.h>
#include <cstdint>

#define B 128
#define S 1024
#define H 256
#define V 256

// Scratch (device globals: allocation-free rule)
__device__ unsigned g_hpk[(size_t)B * S * H];  // packed (bf16 hi << 16) | bf16 lo
__device__ float g_table[V * H];
__device__ float g_context[B * H];
__device__ float g_ctxout[B * V];
__device__ int   g_is64;
__device__ __nv_bfloat16 g_wah[H * H], g_wal[H * H];  // Wattn hi/lo
__device__ __nv_bfloat16 g_wfh[V * H], g_wfl[V * H];  // Wfc   hi/lo

typedef unsigned long long ull;

#define SWZ(o) ((o) ^ (((o) >> 3) & 0x70))

// ---- packed f32x2 helpers (k_rnn) ------------------------------------------
__device__ __forceinline__ ull fma2(ull a, ull b, ull c) {
    ull d;
    asm("fma.rn.f32x2 %0, %1, %2, %3;" : "=l"(d) : "l"(a), "l"(b), "l"(c));
    return d;
}
__device__ __forceinline__ float2 unpk(ull v) {
    float2 r;
    asm("mov.b64 {%0, %1}, %2;" : "=f"(r.x), "=f"(r.y) : "l"(v));
    return r;
}
__device__ __forceinline__ float tanhfast(float x) {
    float y;
    asm("tanh.approx.f32 %0, %1;" : "=f"(y) : "f"(x));
    return y;
}
__device__ __forceinline__ float hsum2(ull a, ull b) {
    float2 u = unpk(a), v = unpk(b);
    return (u.x + u.y) + (v.x + v.y);
}
__device__ __forceinline__ uint32_t smem_u32(const void* p) {
    uint32_t a;
    asm("{ .reg .u64 t; cvta.to.shared.u64 t, %1; cvt.u32.u64 %0, t; }"
        : "=r"(a) : "l"(p));
    return a;
}

// ---- sm80-class tensor ops (valid on sm_103) --------------------------------
#define LDSM4(r, a)                                                           \
    asm volatile("ldmatrix.sync.aligned.m8n8.x4.shared.b16 {%0,%1,%2,%3}, [%4];" \
        : "=r"((r)[0]), "=r"((r)[1]), "=r"((r)[2]), "=r"((r)[3]) : "r"(a))

#define MMA(d, a, bb)                                                         \
    asm volatile("mma.sync.aligned.m16n8k16.row.col.f32.bf16.bf16.f32 "       \
        "{%0,%1,%2,%3},{%4,%5,%6,%7},{%8,%9},{%0,%1,%2,%3};"                  \
        : "+f"((d)[0]), "+f"((d)[1]), "+f"((d)[2]), "+f"((d)[3])              \
        : "r"((a)[0]), "r"((a)[1]), "r"((a)[2]), "r"((a)[3]),                 \
          "r"((bb)[0]), "r"((bb)[1]))

// ---------------------------------------------------------------------------
// K0: detect int64 vs int32 tokens
// ---------------------------------------------------------------------------
__global__ void k_detect(const unsigned int* __restrict__ xw) {
    __shared__ unsigned int red[32];
    unsigned int acc = 0;
    int tid = threadIdx.x;
    for (int i = tid; i < (B * S) / 2; i += 1024) acc |= xw[2 * i + 1];
    #pragma unroll
    for (int o = 16; o; o >>= 1) acc |= __shfl_xor_sync(0xffffffffu, acc, o);
    if ((tid & 31) == 0) red[tid >> 5] = acc;
    __syncthreads();
    if (tid == 0) {
        unsigned int a = 0;
        #pragma unroll
        for (int w = 0; w < 32; w++) a |= red[w];
        g_is64 = (a == 0) ? 1 : 0;
    }
}

// ---------------------------------------------------------------------------
// K1: table[v][j] = bxh[j] + bhh[j] + embed[v,:]·Wxh[j,:]
// ---------------------------------------------------------------------------
__global__ void k_table(const float* __restrict__ embed,
                        const float* __restrict__ Wxh,
                        const float* __restrict__ bxh,
                        const float* __restrict__ bhh) {
    int v = blockIdx.x, j = threadIdx.x;
    __shared__ float es[H];
    es[j] = embed[v * H + j];
    __syncthreads();
    float a0 = bxh[j] + bhh[j], a1 = 0.f, a2 = 0.f, a3 = 0.f;
    const float4* w4 = (const float4*)(Wxh + j * H);
    const float4* e4 = (const float4*)es;
    #pragma unroll
    for (int i = 0; i < H / 4; i++) {
        float4 w = w4[i], e = e4[i];
        a0 += w.x * e.x; a1 += w.y * e.y; a2 += w.z * e.z; a3 += w.w * e.w;
    }
    g_table[v * H + j] = (a0 + a1) + (a2 + a3);
}

// ---------------------------------------------------------------------------
// K1b: split fp32 weights into hi/lo bf16
// ---------------------------------------------------------------------------
__global__ void k_split(const float* __restrict__ W,
                        __nv_bfloat16* __restrict__ hi,
                        __nv_bfloat16* __restrict__ lo) {
    int i = blockIdx.x * 256 + threadIdx.x;
    float w = W[i];
    __nv_bfloat16 h = __float2bfloat16(w);
    hi[i] = h;
    lo[i] = __float2bfloat16(w - __bfloat162float(h));
}

// ---------------------------------------------------------------------------
// K2: Elman recurrence (proven structure; store packs bf16 hi/lo, 1 STG/step)
// ---------------------------------------------------------------------------
#define KREG 192
#define KSMG 16
#define SMEM_RNN (KSMG * 256 * 16 + 2 * 256 * 4)

__global__ void __launch_bounds__(256, 1)
k_rnn(const void* __restrict__ xraw, const float* __restrict__ Whh) {
    extern __shared__ char smraw[];
    ulonglong2* ws = (ulonglong2*)smraw;
    float* hsm = (float*)(smraw + KSMG * 256 * 16);

    int tid = threadIdx.x, b = blockIdx.x;

    for (int i = tid; i < KSMG * 256; i += 256) {
        int j = i & 255, g = i >> 8;
        ws[i] = *(const ulonglong2*)(Whh + j * H + KREG + 4 * g);
    }
    ull w[96];
    {
        const ulonglong2* p = (const ulonglong2*)(Whh + tid * H);
        #pragma unroll
        for (int i = 0; i < 48; i++) {
            ulonglong2 v = p[i];
            w[2 * i] = v.x; w[2 * i + 1] = v.y;
        }
    }
    hsm[tid] = 0.f;

    int is64 = g_is64;
    const long long* x64 = (const long long*)xraw;
    const int*       x32 = (const int*)xraw;
    __syncthreads();

    int tok0 = is64 ? (int)x64[(size_t)b * S] : x32[b * S];
    float tv = g_table[tok0 * H + tid];
    int tokn = is64 ? (int)x64[(size_t)b * S + 1] : x32[b * S + 1];
    unsigned* hp = g_hpk + (size_t)b * S * H + tid;

    for (int t = 0; t < S; t++) {
        float tvn = (t + 1 < S) ? g_table[tokn * H + tid] : 0.f;
        int tokn2 = (t + 2 < S)
                    ? (is64 ? (int)x64[(size_t)b * S + t + 2] : x32[b * S + t + 2])
                    : 0;

        const ulonglong2* h2 = (const ulonglong2*)(hsm + ((t & 1) << 8));
        ull a0 = 0ull, a1 = 0ull, a2 = 0ull, a3 = 0ull;
        #pragma unroll
        for (int i = 0; i < 48; i++) {
            ulonglong2 hh = h2[i];
            a0 = fma2(w[2 * i],     hh.x, a0);
            a1 = fma2(w[2 * i + 1], hh.y, a1);
        }
        #pragma unroll
        for (int g = 0; g < KSMG; g++) {
            ulonglong2 hv = h2[48 + g];
            ulonglong2 wv = ws[(g << 8) + tid];
            a2 = fma2(wv.x, hv.x, a2);
            a3 = fma2(wv.y, hv.y, a3);
        }
        float s = hsum2(a0, a1) + hsum2(a2, a3) + tv;
        float hn = tanhfast(s);

        hsm[(((t & 1) ^ 1) << 8) + tid] = hn;
        unsigned hb = (unsigned)__bfloat16_as_ushort(__float2bfloat16(hn));
        float fh = __uint_as_float(hb << 16);
        unsigned lb = (unsigned)__bfloat16_as_ushort(__float2bfloat16(hn - fh));
        hp[(size_t)t * H] = (hb << 16) | lb;
        tv = tvn; tokn = tokn2;
        __syncthreads();
    }
}

// ---------------------------------------------------------------------------
// HMMA GEMM common pieces. CTA = 128 rows x 128 s, K=256, 8 warps (4j x 2s).
// SMEM: A hi [0,64K), A lo [64K,128K): 4 chunks x [128 rows][64 k] SW128 bf16.
//       B at 128K: double buffer x (hi 16K + lo 16K) = [128 s][64 k] SW128.
//       attn merge scratch at 192K.
// ---------------------------------------------------------------------------
#define SMA_LO 65536
#define SMB 131072
#define SMMERGE 196608
#define SMEM_TC (SMMERGE + 128 * 9 * 3 * 4)

__device__ __forceinline__ void stage_A(char* smA,
                                        const __nv_bfloat16* __restrict__ W,
                                        int tid) {
    #pragma unroll
    for (int it = 0; it < 16; it++) {
        int idx = it * 256 + tid;         // 4096 16B groups total
        int j = idx >> 5, kg = idx & 31;
        uint4 v = *(const uint4*)(W + ((size_t)j << 8) + (kg << 3));
        int c = kg >> 3;                  // 64-k chunk
        int kb = (kg & 7) << 4;           // byte offset in row
        *(uint4*)(smA + c * 16384 + SWZ(j * 128 + kb)) = v;
    }
}

// Load one B chunk (128 s x 64 k packed words) from gmem.
__device__ __forceinline__ void ldgB(uint4* v, const unsigned* __restrict__ rb,
                                     int tid) {
    int s = tid >> 1, q = (tid & 1) * 8;
    const uint4* src = (const uint4*)(rb + (size_t)s * H);
    #pragma unroll
    for (int i = 0; i < 8; i++) v[i] = src[q + i];
}
// Split packed words into hi/lo bf16 SMEM tiles ([128 s][64 k], SW128).
__device__ __forceinline__ void stsB(char* smB, const uint4* v, int tid) {
    int s = tid >> 1, q = (tid & 1) * 8;
    #pragma unroll
    for (int i = 0; i < 8; i++) {
        uint4 u = v[i];
        unsigned h0 = __byte_perm(u.x, u.y, 0x7632);
        unsigned h1 = __byte_perm(u.z, u.w, 0x7632);
        unsigned l0 = __byte_perm(u.x, u.y, 0x5410);
        unsigned l1 = __byte_perm(u.z, u.w, 0x5410);
        int off = SWZ(s * 128 + (q + i) * 8);
        *(ull*)(smB + off)         = ((ull)h1 << 32) | h0;
        *(ull*)(smB + 16384 + off) = ((ull)l1 << 32) | l0;
    }
}

// One K=64 chunk of split-bf16 HMMA into 64 fp32 accumulators (32j x 64s).
__device__ __forceinline__ void mma_chunk(float* acc, uint32_t aB, uint32_t bB,
                                          int cchunk, int wj, int ws, int lane) {
    int r = lane & 7, g = lane >> 3;
    #pragma unroll
    for (int kt = 0; kt < 4; kt++) {
        unsigned ah[2][4], al[2][4];
        #pragma unroll
        for (int mt = 0; mt < 2; mt++) {
            int row = wj * 32 + mt * 16 + (g & 1) * 8 + r;
            int off = cchunk * 16384 + SWZ(row * 128 + kt * 32 + (g >> 1) * 16);
            LDSM4(ah[mt], aB + off);
            LDSM4(al[mt], aB + SMA_LO + off);
        }
        unsigned bh[4][4], bl[4][4];
        #pragma unroll
        for (int pr = 0; pr < 4; pr++) {
            int srow = ws * 64 + pr * 16 + (g >> 1) * 8 + r;
            int off = SWZ(srow * 128 + kt * 32 + (g & 1) * 16);
            LDSM4(bh[pr], bB + off);
            LDSM4(bl[pr], bB + 16384 + off);
        }
        #pragma unroll
        for (int mt = 0; mt < 2; mt++)
            #pragma unroll
            for (int nt = 0; nt < 8; nt++) {
                float* d = acc + (mt * 8 + nt) * 4;
                unsigned* bhp = &bh[nt >> 1][(nt & 1) * 2];
                unsigned* blp = &bl[nt >> 1][(nt & 1) * 2];
                MMA(d, ah[mt], bhp);
                MMA(d, ah[mt], blp);
                MMA(d, al[mt], bhp);
            }
    }
}

// ---------------------------------------------------------------------------
// K3: scores GEMM (HMMA) + online softmax + context. Grid (2, B), 256 thr.
// ---------------------------------------------------------------------------
__global__ void __launch_bounds__(256, 1)
k_attn(const float* __restrict__ battn) {
    extern __shared__ char sm[];
    uint32_t sb = smem_u32(sm);
    int tid = threadIdx.x, lane = tid & 31, w = tid >> 5;
    int wj = w >> 1, ws = w & 1;
    int mrow = lane >> 2, c2 = (lane & 3) * 2;
    int b = blockIdx.y, jbase = blockIdx.x * 128;

    stage_A(sm, g_wah + (size_t)jbase * H, tid);
    stage_A(sm + SMA_LO, g_wal + (size_t)jbase * H, tid);

    const unsigned* hpk = g_hpk + (size_t)b * S * H;

    float bb[4], mx[4], li[4], ci[4];
    #pragma unroll
    for (int mt = 0; mt < 2; mt++)
        #pragma unroll
        for (int rr = 0; rr < 2; rr++) {
            int si = mt * 2 + rr;
            bb[si] = battn[jbase + wj * 32 + mt * 16 + rr * 8 + mrow];
            mx[si] = -1e30f; li[si] = 0.f; ci[si] = 0.f;
        }

    float acc[64];
    #pragma unroll
    for (int i = 0; i < 64; i++) acc[i] = 0.f;

    {   // stage chunk 0
        uint4 v0[8];
        ldgB(v0, hpk, tid);
        stsB(sm + SMB, v0, tid);
    }
    __syncthreads();

    for (int q = 0; q < 32; q++) {
        uint4 nv[8];
        if (q < 31)
            ldgB(nv, hpk + (size_t)((q + 1) >> 2) * 32768 + ((q + 1) & 3) * 64,
                 tid);
        mma_chunk(acc, sb, sb + SMB + (q & 1) * 32768, q & 3, wj, ws, lane);
        if (q < 31)
            stsB(sm + SMB + ((q + 1) & 1) * 32768, nv, tid);
        __syncthreads();

        if ((q & 3) == 3) {
            int sch = q >> 2;
            #pragma unroll
            for (int mt = 0; mt < 2; mt++)
                #pragma unroll
                for (int rr = 0; rr < 2; rr++) {
                    int si = mt * 2 + rr;
                    int jg = jbase + wj * 32 + mt * 16 + rr * 8 + mrow;
                    float sc[16];
                    #pragma unroll
                    for (int nt = 0; nt < 8; nt++) {
                        sc[2 * nt]     = acc[(mt * 8 + nt) * 4 + 2 * rr]     + bb[si];
                        sc[2 * nt + 1] = acc[(mt * 8 + nt) * 4 + 2 * rr + 1] + bb[si];
                    }
                    float nmax = mx[si];
                    #pragma unroll
                    for (int i = 0; i < 16; i++) nmax = fmaxf(nmax, sc[i]);
                    float scale = __expf(mx[si] - nmax);
                    li[si] *= scale; ci[si] *= scale; mx[si] = nmax;
                    #pragma unroll
                    for (int nt = 0; nt < 8; nt++)
                        #pragma unroll
                        for (int col = 0; col < 2; col++) {
                            int sg = sch * 128 + ws * 64 + nt * 8 + c2 + col;
                            unsigned u = hpk[(size_t)sg * H + jg];
                            float hj = __uint_as_float(u & 0xFFFF0000u) +
                                       __uint_as_float(u << 16);
                            float p = __expf(sc[nt * 2 + col] - nmax);
                            li[si] += p; ci[si] += p * hj;
                        }
                }
            #pragma unroll
            for (int i = 0; i < 64; i++) acc[i] = 0.f;
        }
    }

    // merge 8 partials per j (2 s-warps x 4 col-groups)
    float* Mm = (float*)(sm + SMMERGE);
    float* Ml = Mm + 128 * 9;
    float* Mc = Ml + 128 * 9;
    int p8 = ws * 4 + (lane & 3);
    #pragma unroll
    for (int mt = 0; mt < 2; mt++)
        #pragma unroll
        for (int rr = 0; rr < 2; rr++) {
            int jl = wj * 32 + mt * 16 + rr * 8 + mrow;
            int si = mt * 2 + rr;
            Mm[jl * 9 + p8] = mx[si];
            Ml[jl * 9 + p8] = li[si];
            Mc[jl * 9 + p8] = ci[si];
        }
    __syncthreads();
    if (tid < 128) {
        float bm = -1e30f;
        #pragma unroll
        for (int p = 0; p < 8; p++) bm = fmaxf(bm, Mm[tid * 9 + p]);
        float L = 0.f, C = 0.f;
        #pragma unroll
        for (int p = 0; p < 8; p++) {
            float e = __expf(Mm[tid * 9 + p] - bm);
            L += Ml[tid * 9 + p] * e;
            C += Mc[tid * 9 + p] * e;
        }
        g_context[b * H + jbase + tid] = C / L;
    }
}

// ---------------------------------------------------------------------------
// K3b: ctxout[b][v] = bfc[v] + context[b,:]·Wfc[v,:]
// ---------------------------------------------------------------------------
__global__ void k_ctxout(const float* __restrict__ Wfc,
                         const float* __restrict__ bfc) {
    int b = blockIdx.x, v = threadIdx.x;
    __shared__ float cs[H];
    cs[v] = g_context[b * H + v];
    __syncthreads();
    float a0 = bfc[v], a1 = 0.f, a2 = 0.f, a3 = 0.f;
    const float4* w4 = (const float4*)(Wfc + v * H);
    const float4* c4 = (const float4*)cs;
    #pragma unroll
    for (int i = 0; i < H / 4; i++) {
        float4 w = w4[i], cc = c4[i];
        a0 += w.x * cc.x; a1 += w.y * cc.y; a2 += w.z * cc.z; a3 += w.w * cc.w;
    }
    g_ctxout[b * V + v] = (a0 + a1) + (a2 + a3);
}

// ---------------------------------------------------------------------------
// K4: output GEMM (HMMA). Grid (2, B), 256 thr.
// ---------------------------------------------------------------------------
__global__ void __launch_bounds__(256, 1)
k_out(float* __restrict__ out) {
    extern __shared__ char sm[];
    uint32_t sb = smem_u32(sm);
    int tid = threadIdx.x, lane = tid & 31, w = tid >> 5;
    int wj = w >> 1, ws = w & 1;
    int mrow = lane >> 2, c2 = (lane & 3) * 2;
    int b = blockIdx.y, vbase = blockIdx.x * 128;

    stage_A(sm, g_wfh + (size_t)vbase * H, tid);
    stage_A(sm + SMA_LO, g_wfl + (size_t)vbase * H, tid);

    const unsigned* hpk = g_hpk + (size_t)b * S * H;
    float* ob = out + (size_t)b * S * V;

    float cv[4];
    #pragma unroll
    for (int mt = 0; mt < 2; mt++)
        #pragma unroll
        for (int rr = 0; rr < 2; rr++)
            cv[mt * 2 + rr] =
                g_ctxout[b * V + vbase + wj * 32 + mt * 16 + rr * 8 + mrow];

    float acc[64];
    #pragma unroll
    for (int i = 0; i < 64; i++) acc[i] = 0.f;

    {
        uint4 v0[8];
        ldgB(v0, hpk, tid);
        stsB(sm + SMB, v0, tid);
    }
    __syncthreads();

    for (int q = 0; q < 32; q++) {
        uint4 nv[8];
        if (q < 31)
            ldgB(nv, hpk + (size_t)((q + 1) >> 2) * 32768 + ((q + 1) & 3) * 64,
                 tid);
        mma_chunk(acc, sb, sb + SMB + (q & 1) * 32768, q & 3, wj, ws, lane);
        if (q < 31)
            stsB(sm + SMB + ((q + 1) & 1) * 32768, nv, tid);
        __syncthreads();

        if ((q & 3) == 3) {
            int sch = q >> 2;
            #pragma unroll
            for (int mt = 0; mt < 2; mt++)
                #pragma unroll
                for (int nt = 0; nt < 8; nt++) {
                    int s0 = sch * 128 + ws * 64 + nt * 8 + c2;
                    int v0 = vbase + wj * 32 + mt * 16 + mrow;
                    const float* d = acc + (mt * 8 + nt) * 4;
                    ob[(size_t)s0 * V + v0]           = d[0] + cv[mt * 2];
                    ob[(size_t)(s0 + 1) * V + v0]     = d[1] + cv[mt * 2];
                    ob[(size_t)s0 * V + v0 + 8]       = d[2] + cv[mt * 2 + 1];
                    ob[(size_t)(s0 + 1) * V + v0 + 8] = d[3] + cv[mt * 2 + 1];
                }
            #pragma unroll
            for (int i = 0; i < 64; i++) acc[i] = 0.f;
        }
    }
}

// ---------------------------------------------------------------------------
extern "C" void kernel_launch(void* const* d_in, const int* in_sizes, int n_in,
                              void* d_out, int out_size) {
    const void*  x     = d_in[0];
    const float* embed = (const float*)d_in[1];
    const float* Wxh   = (const float*)d_in[2];
    const float* bxh   = (const float*)d_in[3];
    const float* Whh   = (const float*)d_in[4];
    const float* bhh   = (const float*)d_in[5];
    const float* Wattn = (const float*)d_in[6];
    const float* battn = (const float*)d_in[7];
    const float* Wfc   = (const float*)d_in[8];
    const float* bfc   = (const float*)d_in[9];
    float* out = (float*)d_out;

    cudaFuncSetAttribute(k_rnn, cudaFuncAttributeMaxDynamicSharedMemorySize,
                         SMEM_RNN);
    cudaFuncSetAttribute(k_attn, cudaFuncAttributeMaxDynamicSharedMemorySize,
                         SMEM_TC);
    cudaFuncSetAttribute(k_out, cudaFuncAttributeMaxDynamicSharedMemorySize,
                         SMEM_TC);

    __nv_bfloat16 *wah, *wal, *wfh, *wfl;
    cudaGetSymbolAddress((void**)&wah, g_wah);
    cudaGetSymbolAddress((void**)&wal, g_wal);
    cudaGetSymbolAddress((void**)&wfh, g_wfh);
    cudaGetSymbolAddress((void**)&wfl, g_wfl);

    k_detect<<<1, 1024>>>((const unsigned int*)x);
    k_table<<<V, H>>>(embed, Wxh, bxh, bhh);
    k_split<<<H * H / 256, 256>>>(Wattn, wah, wal);
    k_split<<<V * H / 256, 256>>>(Wfc, wfh, wfl);
    k_rnn<<<B, 256, SMEM_RNN>>>(x, Whh);
    k_attn<<<dim3(2, B), 256, SMEM_TC>>>(battn);
    k_ctxout<<<B, V>>>(Wfc, bfc);
    k_out<<<dim3(2, B), 256, SMEM_TC>>>(out);
}